// round 9
// baseline (speedup 1.0000x reference)
#include <cuda_runtime.h>
#include <cuda_bf16.h>

// ---------------------------------------------------------------------------
// GCN_33114197852819 : 4-layer GCN, B=65536, N=12, feats 256->512->256->128->40
// Round 3: register-blocked f32x2 kernel. Each thread: 6 rows x NC cols.
// LDS:FMA2 = 1:4 (was 1:1) -> FMA-pipe bound. Node mixing via shfl.xor(16).
// W pre-packed into float4 quads (4 consecutive K per column) by prep kernel.
// ---------------------------------------------------------------------------

#define NB_TOTAL 65536

typedef unsigned long long ull;

// Packed W quads: L1 [64][512] | L2 [128][256] | L3 [64][128] | L4 [32][64 pad]
#define WQ_L1 0
#define WQ_L2 32768
#define WQ_L3 65536
#define WQ_L4 73728
__device__ float4 g_Wq[75776];
__device__ float g_A[576];       // 4 x 12 x 12 mixing matrices
__device__ float g_b4p[64];      // padded layer-4 bias

__global__ void precompute_A(const float* __restrict__ adj,
                             const float* __restrict__ nv1,
                             const float* __restrict__ nv2,
                             const float* __restrict__ a1,
                             const float* __restrict__ a2,
                             const float* __restrict__ a3,
                             const float* __restrict__ a4,
                             const float* __restrict__ b4)
{
    int n = threadIdx.x;
    if (n < 64) g_b4p[n] = (n < 40) ? b4[n] : 0.f;
    if (n >= 12) return;
    float r[12];
    float mx = -1e30f;
    for (int m = 0; m < 12; m++) {
        float s = 0.f;
        for (int k = 0; k < 10; k++) s += nv1[n * 10 + k] * nv2[k * 12 + m];
        s = fmaxf(s, 0.f);
        r[m] = s;
        mx = fmaxf(mx, s);
    }
    float den = 0.f;
    for (int m = 0; m < 12; m++) { r[m] = expf(r[m] - mx); den += r[m]; }
    float inv = 1.f / den;
    for (int m = 0; m < 12; m++) {
        float av = adj[n * 12 + m] + r[m] * inv;
        g_A[0 * 144 + n * 12 + m] = a1[n * 12 + m] * av;
        g_A[1 * 144 + n * 12 + m] = a2[n * 12 + m] * av;
        g_A[2 * 144 + n * 12 + m] = a3[n * 12 + m] * av;
        g_A[3 * 144 + n * 12 + m] = a4[n * 12 + m] * av;
    }
}

// Pack W[K][O] row-major -> quads q[k4][c] = (W[4k4][c],W[4k4+1][c],W[4k4+2][c],W[4k4+3][c])
__global__ void pack_W(const float* __restrict__ W, int K, int O, int Opad,
                       int dstOff)
{
    int idx = blockIdx.x * blockDim.x + threadIdx.x;
    int total = (K / 4) * Opad;
    if (idx >= total) return;
    int k4 = idx / Opad;
    int c = idx % Opad;
    float4 q = make_float4(0.f, 0.f, 0.f, 0.f);
    if (c < O) {
        q.x = W[(4 * k4 + 0) * O + c];
        q.y = W[(4 * k4 + 1) * O + c];
        q.z = W[(4 * k4 + 2) * O + c];
        q.w = W[(4 * k4 + 3) * O + c];
    }
    g_Wq[dstOff + idx] = q;
}

// ---- packed f32x2 helpers -------------------------------------------------
__device__ __forceinline__ ull f2pack(float x, float y)
{
    ull r;
    asm("mov.b64 %0, {%1, %2};" : "=l"(r) : "f"(x), "f"(y));
    return r;
}
__device__ __forceinline__ void f2fma(ull& d, ull a, ull b)
{
    asm("fma.rn.f32x2 %0, %1, %2, %0;" : "+l"(d) : "l"(a), "l"(b));
}
__device__ __forceinline__ float f2sum(ull v)
{
    float x, y;
    asm("mov.b64 {%0, %1}, %2;" : "=f"(x), "=f"(y) : "l"(v));
    return x + y;
}

// ---- one GCN layer --------------------------------------------------------
// in : SMEM [24 rows][K+2 stride], row = bt*12 + node
// Wq : packed quads [K/4][Opad]
// Thread (bt, rh, cg): rows rh*6..rh*6+5 of batch bt, cols c = coff+cg+64*j.
// Mixing: partials for all 12 output nodes, halves combined via shfl.xor(16).
template <int K, int O, int NC, int Opad, bool FINAL>
__device__ __forceinline__ void layer(const float* __restrict__ in,
                                      float* __restrict__ outbuf,
                                      const float4* __restrict__ Wq,
                                      const float* __restrict__ bias,
                                      const float* __restrict__ A,
                                      float* __restrict__ gout,
                                      long long b0, int coff,
                                      int cg, int rh, int bt)
{
    constexpr int IS = K + 2;   // input stride
    const float* hrow = in + (bt * 12 + rh * 6) * IS;
    const float4* wp = Wq + coff + cg;

    ull acc[6][NC];
#pragma unroll
    for (int r = 0; r < 6; r++)
#pragma unroll
        for (int j = 0; j < NC; j++) acc[r][j] = 0ull;

#pragma unroll 2
    for (int k4 = 0; k4 < K / 4; k4++) {
        ull wA[NC], wB[NC];
#pragma unroll
        for (int j = 0; j < NC; j++) {
            float4 w = __ldg(wp + k4 * Opad + 64 * j);
            wA[j] = f2pack(w.x, w.y);
            wB[j] = f2pack(w.z, w.w);
        }
        const float* hp = hrow + 4 * k4;
#pragma unroll
        for (int r = 0; r < 6; r++) {
            ull hA = *(const ull*)(hp + r * IS);
            ull hB = *(const ull*)(hp + r * IS + 2);
#pragma unroll
            for (int j = 0; j < NC; j++) {
                f2fma(acc[r][j], hA, wA[j]);
                f2fma(acc[r][j], hB, wB[j]);
            }
        }
    }

    float S[6][NC];
#pragma unroll
    for (int r = 0; r < 6; r++)
#pragma unroll
        for (int j = 0; j < NC; j++) S[r][j] = f2sum(acc[r][j]);

    // partial mixing: contributions of my 6 m-rows to all 12 output nodes
    float pLo[6][NC], pHi[6][NC];
#pragma unroll
    for (int n = 0; n < 6; n++)
#pragma unroll
        for (int j = 0; j < NC; j++) { pLo[n][j] = 0.f; pHi[n][j] = 0.f; }

    const float* Am = A + rh * 6;   // A[n*12 + rh*6 + i]
#pragma unroll
    for (int i = 0; i < 6; i++) {
#pragma unroll
        for (int n = 0; n < 6; n++) {
            float aLo = Am[n * 12 + i];
            float aHi = Am[(n + 6) * 12 + i];
#pragma unroll
            for (int j = 0; j < NC; j++) {
                pLo[n][j] = fmaf(aLo, S[i][j], pLo[n][j]);
                pHi[n][j] = fmaf(aHi, S[i][j], pHi[n][j]);
            }
        }
    }

    float bj[NC];
#pragma unroll
    for (int j = 0; j < NC; j++) bj[j] = __ldg(bias + coff + cg + 64 * j);

#pragma unroll
    for (int n = 0; n < 6; n++) {
#pragma unroll
        for (int j = 0; j < NC; j++) {
            float send = rh ? pLo[n][j] : pHi[n][j];
            float keep = rh ? pHi[n][j] : pLo[n][j];
            float tot = keep + __shfl_xor_sync(0xffffffffu, send, 16);
            float v = fmaxf(tot + bj[j], 0.f);
            int c = coff + cg + 64 * j;
            int node = rh * 6 + n;
            if (FINAL) {
                if (c < 40) gout[((b0 + bt) * 12 + node) * 40 + c] = v;
            } else {
                outbuf[(bt * 12 + node) * (O + 2) + c] = v;
            }
        }
    }
}

// SMEM: bufA 24*514 = 12336 | bufB 24*258 = 6192 | A 576  -> 19104 floats
#define SMEM_FLOATS (12336 + 6192 + 576)

__global__ __launch_bounds__(256, 2) void gcn_main(
    const float* __restrict__ x,
    const float* __restrict__ b1, const float* __restrict__ b2,
    const float* __restrict__ b3,
    float* __restrict__ out)
{
    extern __shared__ float sm[];
    float* bufA = sm;                 // stride 514 (h1); reused stride 130 (h3)
    float* bufB = sm + 12336;         // stride 258 (x, h2)
    float* Ash  = sm + 12336 + 6192;

    const int tid = threadIdx.x;
    const long long b0 = (long long)blockIdx.x * 2;

    const int cg = (tid & 15) | (((tid >> 5) & 3) << 4);  // 0..63
    const int rh = (tid >> 4) & 1;                        // row half (in-warp)
    const int bt = tid >> 7;                              // batch within tile

    for (int i = tid; i < 576; i += 256) Ash[i] = g_A[i];

    // load x tile: 24 rows x 256 cols into bufB (stride 258), as float2
    {
        const float2* xs = (const float2*)(x + b0 * (12 * 256));
        for (int i = tid; i < 3072; i += 256) {
            int r = i >> 7;
            int cp = i & 127;
            *(float2*)(bufB + r * 258 + 2 * cp) = xs[(size_t)r * 128 + cp];
        }
    }
    __syncthreads();

    // L1: K=256 O=512, two column iterations of 256
    layer<256, 512, 4, 512, false>(bufB, bufA, g_Wq + WQ_L1, b1, Ash + 0,
                                   nullptr, b0, 0, cg, rh, bt);
    layer<256, 512, 4, 512, false>(bufB, bufA, g_Wq + WQ_L1, b1, Ash + 0,
                                   nullptr, b0, 256, cg, rh, bt);
    __syncthreads();   // bufA (h1) complete

    // L2: K=512 O=256 ; epilogue overwrites bufB -> sync inside via 2 phases
    {
        // K-loop reads bufA, epilogue writes bufB (x no longer needed, but
        // ensure all K-loop reads of bufA done before... bufA untouched; bufB
        // overwrite is safe only after all threads stop reading bufB -- bufB
        // was last read in L1 (already synced).  So direct call is fine.
        layer<512, 256, 4, 256, false>(bufA, bufB, g_Wq + WQ_L2, b2, Ash + 144,
                                       nullptr, b0, 0, cg, rh, bt);
    }
    __syncthreads();   // bufB (h2) complete

    // L3: K=256 O=128, NC=2 ; epilogue writes into bufA region (stride 130)
    layer<256, 128, 2, 128, false>(bufB, bufA, g_Wq + WQ_L3, b3, Ash + 288,
                                   nullptr, b0, 0, cg, rh, bt);
    __syncthreads();   // bufA (h3, stride 130) complete

    // L4: K=128 O=40 (padded 64), NC=1, final -> global
    layer<128, 40, 1, 64, true>(bufA, nullptr, g_Wq + WQ_L4, g_b4p, Ash + 432,
                                out, b0, 0, cg, rh, bt);
}

extern "C" void kernel_launch(void* const* d_in, const int* in_sizes, int n_in,
                              void* d_out, int out_size)
{
    const float* x    = (const float*)d_in[0];
    const float* adj  = (const float*)d_in[1];
    const float* nv1  = (const float*)d_in[2];
    const float* nv2  = (const float*)d_in[3];
    const float* W1   = (const float*)d_in[4];
    const float* att1 = (const float*)d_in[5];
    const float* b1   = (const float*)d_in[6];
    const float* W2   = (const float*)d_in[7];
    const float* att2 = (const float*)d_in[8];
    const float* b2   = (const float*)d_in[9];
    const float* W3   = (const float*)d_in[10];
    const float* att3 = (const float*)d_in[11];
    const float* b3   = (const float*)d_in[12];
    const float* W4   = (const float*)d_in[13];
    const float* att4 = (const float*)d_in[14];
    const float* b4   = (const float*)d_in[15];
    float* out = (float*)d_out;

    precompute_A<<<1, 64>>>(adj, nv1, nv2, att1, att2, att3, att4, b4);
    pack_W<<<(64 * 512 + 255) / 256, 256>>>(W1, 256, 512, 512, WQ_L1);
    pack_W<<<(128 * 256 + 255) / 256, 256>>>(W2, 512, 256, 256, WQ_L2);
    pack_W<<<(64 * 128 + 255) / 256, 256>>>(W3, 256, 128, 128, WQ_L3);
    pack_W<<<(32 * 64 + 255) / 256, 256>>>(W4, 128, 40, 64, WQ_L4);

    const size_t smem = SMEM_FLOATS * sizeof(float);
    cudaFuncSetAttribute(gcn_main, cudaFuncAttributeMaxDynamicSharedMemorySize,
                         (int)smem);
    gcn_main<<<NB_TOTAL / 2, 256, smem>>>(x, b1, b2, b3, out);
}

// round 11
// speedup vs baseline: 1.4183x; 1.4183x over previous
#include <cuda_runtime.h>
#include <cuda_bf16.h>
#include <cstdint>

typedef unsigned long long ull;

#define PASSB 16384
#define NPASS 4

__device__ float g_A[576];          // 4 x 12x12 premix matrices
__device__ float g_b4p[64];         // padded layer-4 bias
__device__ float g_W4p[128 * 64];   // padded layer-4 W
// packed W slabs: per (n-chunk, k32): [hi NCH x 32 bf16 | lo ...], SW128
__device__ __align__(1024) uint8_t g_Wp[1245184];
#define WP_L1 0u
#define WP_L2 524288u
#define WP_L3 1048576u
#define WP_L4 1179648u

__device__ float g_h1[(size_t)PASSB * 12 * 512];
__device__ float g_h2[(size_t)PASSB * 12 * 256];
__device__ float g_h3[(size_t)PASSB * 12 * 128];

// ---------------------------------------------------------------------------
__global__ void precompute_A(const float* __restrict__ adj,
                             const float* __restrict__ nv1,
                             const float* __restrict__ nv2,
                             const float* __restrict__ a1,
                             const float* __restrict__ a2,
                             const float* __restrict__ a3,
                             const float* __restrict__ a4,
                             const float* __restrict__ b4)
{
    int n = threadIdx.x;
    if (n < 64) g_b4p[n] = (n < 40) ? b4[n] : 0.f;
    if (n >= 12) return;
    float r[12];
    float mx = -1e30f;
    for (int m = 0; m < 12; m++) {
        float s = 0.f;
        for (int k = 0; k < 10; k++) s += nv1[n * 10 + k] * nv2[k * 12 + m];
        s = fmaxf(s, 0.f);
        r[m] = s;
        mx = fmaxf(mx, s);
    }
    float den = 0.f;
    for (int m = 0; m < 12; m++) { r[m] = expf(r[m] - mx); den += r[m]; }
    float inv = 1.f / den;
    for (int m = 0; m < 12; m++) {
        float av = adj[n * 12 + m] + r[m] * inv;
        g_A[0 * 144 + n * 12 + m] = a1[n * 12 + m] * av;
        g_A[1 * 144 + n * 12 + m] = a2[n * 12 + m] * av;
        g_A[2 * 144 + n * 12 + m] = a3[n * 12 + m] * av;
        g_A[3 * 144 + n * 12 + m] = a4[n * 12 + m] * av;
    }
}

__global__ void pad_W4(const float* __restrict__ W4, float* __restrict__ dst)
{
    int idx = blockIdx.x * blockDim.x + threadIdx.x;
    if (idx >= 128 * 64) return;
    int k = idx / 64, o = idx % 64;
    dst[idx] = (o < 40) ? W4[k * 40 + o] : 0.f;
}

// W[K][O] row-major -> slabs [(nc,kc)]: hi plane [NCH][32k] + lo plane, SW128
__global__ void pack_Wsplit(const float* __restrict__ W, int K, int O, int NCH,
                            unsigned base)
{
    int idx = blockIdx.x * blockDim.x + threadIdx.x;
    if (idx >= K * O) return;
    int k = idx / O, o = idx % O;
    float w = W[idx];
    __nv_bfloat16 hi = __float2bfloat16(w);
    __nv_bfloat16 lo = __float2bfloat16(w - __bfloat162float(hi));
    int nc = o / NCH, ln = o % NCH, kc = k / 32, kk = k & 31;
    unsigned slab = base + (unsigned)(nc * (K / 32) + kc) * (unsigned)(NCH * 128);
    unsigned off = (unsigned)ln * 64u + (unsigned)kk * 2u;
    unsigned sw = off ^ ((off >> 3) & 0x70u);
    *(__nv_bfloat16*)(g_Wp + slab + sw) = hi;
    *(__nv_bfloat16*)(g_Wp + slab + (unsigned)(NCH * 64) + sw) = lo;
}

// ---------------------------------------------------------------------------
__device__ __forceinline__ uint32_t smem_u32(const void* p)
{
    uint32_t a;
    asm("{ .reg .u64 t; cvta.to.shared.u64 t, %1; cvt.u32.u64 %0, t; }"
        : "=r"(a) : "l"(p));
    return a;
}
__device__ __forceinline__ ull f2pack(float x, float y)
{
    ull r; asm("mov.b64 %0, {%1, %2};" : "=l"(r) : "f"(x), "f"(y)); return r;
}
__device__ __forceinline__ void f2fma(ull& d, ull a, ull b)
{
    asm("fma.rn.f32x2 %0, %1, %2, %0;" : "+l"(d) : "l"(a), "l"(b));
}
__device__ __forceinline__ float2 f2unp(ull v)
{
    float2 r; asm("mov.b64 {%0, %1}, %2;" : "=f"(r.x), "=f"(r.y) : "l"(v));
    return r;
}
__device__ __forceinline__ uint32_t bf2pack(float lo, float hi)
{
    uint32_t r;
    asm("cvt.rn.bf16x2.f32 %0, %1, %2;" : "=r"(r) : "f"(hi), "f"(lo));
    return r;
}
__device__ __forceinline__ void mwait(uint32_t mbar, uint32_t parity)
{
    asm volatile(
        "{\n\t.reg .pred P;\n\tWL_%=:\n\t"
        "mbarrier.try_wait.parity.shared.b64 P, [%0], %1;\n\t"
        "@!P bra WL_%=;\n\t}"
        :: "r"(mbar), "r"(parity) : "memory");
}
__device__ __forceinline__ void bulk_g2s(uint32_t dst, const void* src,
                                         uint32_t bytes, uint32_t mbar)
{
    asm volatile(
        "cp.async.bulk.shared::cta.global.mbarrier::complete_tx::bytes "
        "[%0], [%1], %2, [%3];"
        :: "r"(dst), "l"(src), "r"(bytes), "r"(mbar) : "memory");
}
__device__ __forceinline__ void ldsm4(uint32_t a, uint32_t* r)
{
    asm volatile("ldmatrix.sync.aligned.m8n8.x4.shared.b16 {%0,%1,%2,%3}, [%4];"
                 : "=r"(r[0]), "=r"(r[1]), "=r"(r[2]), "=r"(r[3]) : "r"(a));
}
#define MBAR_INIT(a) \
    asm volatile("mbarrier.init.shared.b64 [%0], 1;" :: "r"(a) : "memory")
#define MBAR_EXPECT(a, b) \
    asm volatile("mbarrier.arrive.expect_tx.shared.b64 _, [%0], %1;" \
                 :: "r"(a), "r"(b) : "memory")
#define STSV4(a, p) \
    asm volatile("st.shared.v4.b32 [%0], {%1,%2,%3,%4};" \
                 :: "r"(a), "r"((p)[0]), "r"((p)[1]), "r"((p)[2]), "r"((p)[3]) \
                 : "memory")
#define MMA(d, a, b) \
    asm volatile("mma.sync.aligned.m16n8k16.row.col.f32.bf16.bf16.f32 " \
                 "{%0,%1,%2,%3}, {%4,%5,%6,%7}, {%8,%9}, {%0,%1,%2,%3};" \
                 : "+f"((d)[0]), "+f"((d)[1]), "+f"((d)[2]), "+f"((d)[3]) \
                 : "r"((a)[0]), "r"((a)[1]), "r"((a)[2]), "r"((a)[3]), \
                   "r"((b)[0]), "r"((b)[1]))

// ---------------------------------------------------------------------------
// One layer: dst = relu( premix(A, src) @ W + b )
// A tile (MT x KK) premixed+split into SMEM slabs; B streamed via bulk copies.
// ---------------------------------------------------------------------------
template <int MT, int KK, int OO, int NCH, int WM, int WN, bool FINAL>
__global__ __launch_bounds__(256) void gemm_layer(
    const float* __restrict__ src, float* __restrict__ dst,
    const float* __restrict__ bias, const uint8_t* __restrict__ wsrc, int aidx)
{
    constexpr int NCK = KK / 32;
    constexpr int NNC = OO / NCH;
    constexpr int NSTEP = NNC * NCK;
    constexpr int WTN = NCH / WN;
    constexpr int MI = 2;
    constexpr int NJ = WTN / 8;
    constexpr int NJ4 = NJ / 2;
    constexpr int ASLAB = MT * 128;
    constexpr int BSLAB = NCH * 128;
    constexpr int ABYTES = NCK * ASLAB;
    constexpr int BPT = (MT == 128) ? 10 : 5;
    constexpr int VR = BPT * 12;

    extern __shared__ uint8_t smem[];
    __shared__ ull mbar[2];
    const uint32_t Ab = smem_u32(smem);
    const uint32_t Bb = Ab + ABYTES;
    const uint32_t mb0 = smem_u32(&mbar[0]), mb1 = smem_u32(&mbar[1]);
    const int tid = threadIdx.x, l = tid & 31, w = tid >> 5;
    const int wm = w / WN, wn = w % WN;
    const int tile = blockIdx.x;

    if (tid == 0) {
        MBAR_INIT(mb0); MBAR_INIT(mb1);
        MBAR_EXPECT(mb0, BSLAB);
        bulk_g2s(Bb, wsrc, BSLAB, mb0);
    }

    // ---------------- premix A tile into SMEM (hi/lo bf16, SW128) ----------
    {
        constexpr int TPR = 256 / MT;
        constexpr int PIECES = KK / (32 * TPR);
        const int r = tid / TPR, part = tid % TPR;
        const int nn = r % 12;
        const long batch = (long)tile * BPT + r / 12;
        const bool valid = (r < VR) && (batch < PASSB);
        const float* srow = src + (size_t)batch * 12 * KK;
        float am[12];
#pragma unroll
        for (int m = 0; m < 12; m++) am[m] = g_A[aidx + nn * 12 + m];
#pragma unroll 1
        for (int p = 0; p < PIECES; p++) {
            const int kc = part * PIECES + p;
            ull acc[16];
#pragma unroll
            for (int i = 0; i < 16; i++) acc[i] = 0ull;
            if (valid) {
#pragma unroll
                for (int m = 0; m < 12; m++) {
                    const float4* sp =
                        (const float4*)(srow + (size_t)m * KK + kc * 32);
                    ull amm = f2pack(am[m], am[m]);
#pragma unroll
                    for (int q = 0; q < 8; q++) {
                        float4 f = __ldg(sp + q);
                        f2fma(acc[2 * q], f2pack(f.x, f.y), amm);
                        f2fma(acc[2 * q + 1], f2pack(f.z, f.w), amm);
                    }
                }
            }
            uint32_t hw[16], lw[16];
#pragma unroll
            for (int i = 0; i < 16; i++) {
                float2 f = f2unp(acc[i]);
                uint32_t h = bf2pack(f.x, f.y);
                float v0 = __uint_as_float(h << 16);
                float v1 = __uint_as_float(h & 0xffff0000u);
                lw[i] = bf2pack(f.x - v0, f.y - v1);
                hw[i] = h;
            }
            const uint32_t base = Ab + kc * ASLAB;
#pragma unroll
            for (int q4 = 0; q4 < 4; q4++) {
                uint32_t off = (uint32_t)r * 64u + q4 * 16u;
                uint32_t sw = off ^ ((off >> 3) & 0x70u);
                STSV4(base + sw, hw + 4 * q4);
                STSV4(base + MT * 64 + sw, lw + 4 * q4);
            }
        }
    }

    // ldmatrix per-lane byte offsets (within slab plane)
    uint32_t aoff[MI][2], boff[NJ4][2];
    {
        const int ar = wm * 32 + (l & 15);
        const int kh = l >> 4;
#pragma unroll
        for (int mi = 0; mi < MI; mi++)
#pragma unroll
            for (int k16 = 0; k16 < 2; k16++) {
                uint32_t off = (uint32_t)(ar + mi * 16) * 64u + k16 * 32u + kh * 16u;
                aoff[mi][k16] = off ^ ((off >> 3) & 0x70u);
            }
        const int br = wn * WTN + (l & 7) + 8 * (l >> 4);
        const int bk = (l >> 3) & 1;
#pragma unroll
        for (int j = 0; j < NJ4; j++)
#pragma unroll
            for (int k16 = 0; k16 < 2; k16++) {
                uint32_t off = (uint32_t)(br + j * 16) * 64u + k16 * 32u + bk * 16u;
                boff[j][k16] = off ^ ((off >> 3) & 0x70u);
            }
    }

    float acc[MI][NJ][4];
#pragma unroll
    for (int mi = 0; mi < MI; mi++)
#pragma unroll
        for (int nj = 0; nj < NJ; nj++)
#pragma unroll
            for (int q = 0; q < 4; q++) acc[mi][nj][q] = 0.f;

    long remv = ((long)PASSB - (long)tile * BPT) * 12;
    const int vrows = (remv > VR) ? VR : (int)remv;

    for (int s = 0; s < NSTEP; s++) {
        __syncthreads();
        if (tid == 0 && s + 1 < NSTEP) {
            uint32_t b = (s + 1) & 1;
            MBAR_EXPECT(b ? mb1 : mb0, BSLAB);
            bulk_g2s(Bb + b * BSLAB, wsrc + (size_t)(s + 1) * BSLAB, BSLAB,
                     b ? mb1 : mb0);
        }
        mwait((s & 1) ? mb1 : mb0, (s >> 1) & 1);
        const uint32_t asl = Ab + (s % NCK) * ASLAB;
        const uint32_t bsl = Bb + (s & 1) * BSLAB;
#pragma unroll
        for (int k16 = 0; k16 < 2; k16++) {
            uint32_t Ah[MI][4], Al[MI][4], Bh[NJ4][4], Bl[NJ4][4];
#pragma unroll
            for (int mi = 0; mi < MI; mi++) {
                ldsm4(asl + aoff[mi][k16], Ah[mi]);
                ldsm4(asl + MT * 64 + aoff[mi][k16], Al[mi]);
            }
#pragma unroll
            for (int j = 0; j < NJ4; j++) {
                ldsm4(bsl + boff[j][k16], Bh[j]);
                ldsm4(bsl + NCH * 64 + boff[j][k16], Bl[j]);
            }
#pragma unroll
            for (int mi = 0; mi < MI; mi++)
#pragma unroll
                for (int j = 0; j < NJ4; j++) {
                    MMA(acc[mi][2 * j], Ah[mi], &Bh[j][0]);
                    MMA(acc[mi][2 * j + 1], Ah[mi], &Bh[j][2]);
                    MMA(acc[mi][2 * j], Ah[mi], &Bl[j][0]);
                    MMA(acc[mi][2 * j + 1], Ah[mi], &Bl[j][2]);
                    MMA(acc[mi][2 * j], Al[mi], &Bh[j][0]);
                    MMA(acc[mi][2 * j + 1], Al[mi], &Bh[j][2]);
                }
        }
        if ((s % NCK) == NCK - 1) {
            const int nc = s / NCK;
            constexpr size_t OSTR = FINAL ? 40 : OO;
#pragma unroll
            for (int mi = 0; mi < MI; mi++)
#pragma unroll
                for (int nj = 0; nj < NJ; nj++) {
                    const int r0 = wm * 32 + mi * 16 + (l >> 2);
                    const int c0 = nc * NCH + wn * WTN + nj * 8 + 2 * (l & 3);
                    float2 bv = *(const float2*)(bias + c0);
                    float v0 = fmaxf(acc[mi][nj][0] + bv.x, 0.f);
                    float v1 = fmaxf(acc[mi][nj][1] + bv.y, 0.f);
                    float v2 = fmaxf(acc[mi][nj][2] + bv.x, 0.f);
                    float v3 = fmaxf(acc[mi][nj][3] + bv.y, 0.f);
                    const bool cok = (!FINAL) || (c0 < 40);
                    const size_t gr = (size_t)tile * VR + r0;
                    if (cok && r0 < vrows)
                        *(float2*)(dst + gr * OSTR + c0) = make_float2(v0, v1);
                    if (cok && r0 + 8 < vrows)
                        *(float2*)(dst + (gr + 8) * OSTR + c0) = make_float2(v2, v3);
#pragma unroll
                    for (int q = 0; q < 4; q++) acc[mi][nj][q] = 0.f;
                }
        }
    }
}

// ---------------------------------------------------------------------------
extern "C" void kernel_launch(void* const* d_in, const int* in_sizes, int n_in,
                              void* d_out, int out_size)
{
    const float* x    = (const float*)d_in[0];
    const float* adj  = (const float*)d_in[1];
    const float* nv1  = (const float*)d_in[2];
    const float* nv2  = (const float*)d_in[3];
    const float* W1   = (const float*)d_in[4];
    const float* att1 = (const float*)d_in[5];
    const float* b1   = (const float*)d_in[6];
    const float* W2   = (const float*)d_in[7];
    const float* att2 = (const float*)d_in[8];
    const float* b2   = (const float*)d_in[9];
    const float* W3   = (const float*)d_in[10];
    const float* att3 = (const float*)d_in[11];
    const float* b3   = (const float*)d_in[12];
    const float* W4   = (const float*)d_in[13];
    const float* att4 = (const float*)d_in[14];
    const float* b4   = (const float*)d_in[15];
    float* out = (float*)d_out;

    void *ph1, *ph2, *ph3, *pb4, *pw4, *pwp;
    cudaGetSymbolAddress(&ph1, g_h1);
    cudaGetSymbolAddress(&ph2, g_h2);
    cudaGetSymbolAddress(&ph3, g_h3);
    cudaGetSymbolAddress(&pb4, g_b4p);
    cudaGetSymbolAddress(&pw4, g_W4p);
    cudaGetSymbolAddress(&pwp, g_Wp);

    precompute_A<<<1, 64>>>(adj, nv1, nv2, att1, att2, att3, att4, b4);
    pad_W4<<<(128 * 64 + 255) / 256, 256>>>(W4, (float*)pw4);
    pack_Wsplit<<<(256 * 512 + 255) / 256, 256>>>(W1, 256, 512, 128, WP_L1);
    pack_Wsplit<<<(512 * 256 + 255) / 256, 256>>>(W2, 512, 256, 128, WP_L2);
    pack_Wsplit<<<(256 * 128 + 255) / 256, 256>>>(W3, 256, 128, 128, WP_L3);
    pack_Wsplit<<<(128 * 64 + 255) / 256, 256>>>((const float*)pw4, 128, 64, 64,
                                                 WP_L4);

    const uint8_t* wp = (const uint8_t*)pwp;
    const int SM1 = 8 * 128 * 128 + 2 * 128 * 128;   // 163840
    const int SM2 = 16 * 64 * 128 + 2 * 128 * 128;   // 163840
    const int SM3 = 8 * 128 * 128 + 2 * 128 * 128;   // 163840
    const int SM4 = 4 * 128 * 128 + 2 * 64 * 128;    // 81920
    cudaFuncSetAttribute((gemm_layer<128, 256, 512, 128, 4, 2, false>),
                         cudaFuncAttributeMaxDynamicSharedMemorySize, SM1);
    cudaFuncSetAttribute((gemm_layer<64, 512, 256, 128, 2, 4, false>),
                         cudaFuncAttributeMaxDynamicSharedMemorySize, SM2);
    cudaFuncSetAttribute((gemm_layer<128, 256, 128, 128, 4, 2, false>),
                         cudaFuncAttributeMaxDynamicSharedMemorySize, SM3);
    cudaFuncSetAttribute((gemm_layer<128, 128, 64, 64, 4, 2, true>),
                         cudaFuncAttributeMaxDynamicSharedMemorySize, SM4);

    const int T1 = 1639, T2 = 3277, T3 = 1639, T4 = 1639;
    for (int p = 0; p < NPASS; p++) {
        const float* xs = x + (size_t)p * PASSB * 12 * 256;
        float* op = out + (size_t)p * PASSB * 12 * 40;
        gemm_layer<128, 256, 512, 128, 4, 2, false><<<T1, 256, SM1>>>(
            xs, (float*)ph1, b1, wp + WP_L1, 0);
        gemm_layer<64, 512, 256, 128, 2, 4, false><<<T2, 256, SM2>>>(
            (const float*)ph1, (float*)ph2, b2, wp + WP_L2, 144);
        gemm_layer<128, 256, 128, 128, 4, 2, false><<<T3, 256, SM3>>>(
            (const float*)ph2, (float*)ph3, b3, wp + WP_L3, 288);
        gemm_layer<128, 128, 64, 64, 4, 2, true><<<T4, 256, SM4>>>(
            (const float*)ph3, op, (float*)pb4, wp + WP_L4, 432);
    }
}

// round 13
// speedup vs baseline: 1.4859x; 1.0477x over previous
#include <cuda_runtime.h>
#include <cuda_bf16.h>
#include <cstdint>

typedef unsigned long long ull;

#define BTOT 65536

__device__ float g_A[576];          // 4 x 12x12 premix matrices
__device__ float g_b4p[64];         // padded layer-4 bias
__device__ float g_W4p[128 * 64];   // padded layer-4 W
// packed W slabs: per (n-chunk, k32): [hi NCH x 32 bf16 | lo ...], SW128
__device__ __align__(1024) uint8_t g_Wp[1245184];
#define WP_L1 0u
#define WP_L2 524288u
#define WP_L3 1048576u
#define WP_L4 1179648u

__device__ float g_h1[(size_t)BTOT * 12 * 512];
__device__ float g_h2[(size_t)BTOT * 12 * 256];
__device__ float g_h3[(size_t)BTOT * 12 * 128];

// ---------------------------------------------------------------------------
__global__ void precompute_A(const float* __restrict__ adj,
                             const float* __restrict__ nv1,
                             const float* __restrict__ nv2,
                             const float* __restrict__ a1,
                             const float* __restrict__ a2,
                             const float* __restrict__ a3,
                             const float* __restrict__ a4,
                             const float* __restrict__ b4)
{
    int n = threadIdx.x;
    if (n < 64) g_b4p[n] = (n < 40) ? b4[n] : 0.f;
    if (n >= 12) return;
    float r[12];
    float mx = -1e30f;
    for (int m = 0; m < 12; m++) {
        float s = 0.f;
        for (int k = 0; k < 10; k++) s += nv1[n * 10 + k] * nv2[k * 12 + m];
        s = fmaxf(s, 0.f);
        r[m] = s;
        mx = fmaxf(mx, s);
    }
    float den = 0.f;
    for (int m = 0; m < 12; m++) { r[m] = expf(r[m] - mx); den += r[m]; }
    float inv = 1.f / den;
    for (int m = 0; m < 12; m++) {
        float av = adj[n * 12 + m] + r[m] * inv;
        g_A[0 * 144 + n * 12 + m] = a1[n * 12 + m] * av;
        g_A[1 * 144 + n * 12 + m] = a2[n * 12 + m] * av;
        g_A[2 * 144 + n * 12 + m] = a3[n * 12 + m] * av;
        g_A[3 * 144 + n * 12 + m] = a4[n * 12 + m] * av;
    }
}

__global__ void pad_W4(const float* __restrict__ W4, float* __restrict__ dst)
{
    int idx = blockIdx.x * blockDim.x + threadIdx.x;
    if (idx >= 128 * 64) return;
    int k = idx / 64, o = idx % 64;
    dst[idx] = (o < 40) ? W4[k * 40 + o] : 0.f;
}

// W[K][O] row-major -> slabs [(nc,kc)]: hi plane [NCH][32k] + lo plane, SW128
__global__ void pack_Wsplit(const float* __restrict__ W, int K, int O, int NCH,
                            unsigned base)
{
    int idx = blockIdx.x * blockDim.x + threadIdx.x;
    if (idx >= K * O) return;
    int k = idx / O, o = idx % O;
    float w = W[idx];
    __nv_bfloat16 hi = __float2bfloat16(w);
    __nv_bfloat16 lo = __float2bfloat16(w - __bfloat162float(hi));
    int nc = o / NCH, ln = o % NCH, kc = k / 32, kk = k & 31;
    unsigned slab = base + (unsigned)(nc * (K / 32) + kc) * (unsigned)(NCH * 128);
    unsigned off = (unsigned)ln * 64u + (unsigned)kk * 2u;
    unsigned sw = off ^ ((off >> 3) & 0x70u);
    *(__nv_bfloat16*)(g_Wp + slab + sw) = hi;
    *(__nv_bfloat16*)(g_Wp + slab + (unsigned)(NCH * 64) + sw) = lo;
}

// ---------------------------------------------------------------------------
__device__ __forceinline__ uint32_t smem_u32(const void* p)
{
    uint32_t a;
    asm("{ .reg .u64 t; cvta.to.shared.u64 t, %1; cvt.u32.u64 %0, t; }"
        : "=r"(a) : "l"(p));
    return a;
}
__device__ __forceinline__ ull f2pack(float x, float y)
{
    ull r; asm("mov.b64 %0, {%1, %2};" : "=l"(r) : "f"(x), "f"(y)); return r;
}
__device__ __forceinline__ void f2fma(ull& d, ull a, ull b)
{
    asm("fma.rn.f32x2 %0, %1, %2, %0;" : "+l"(d) : "l"(a), "l"(b));
}
__device__ __forceinline__ float2 f2unp(ull v)
{
    float2 r; asm("mov.b64 {%0, %1}, %2;" : "=f"(r.x), "=f"(r.y) : "l"(v));
    return r;
}
__device__ __forceinline__ uint32_t bf2pack(float lo, float hi)
{
    uint32_t r;
    asm("cvt.rn.bf16x2.f32 %0, %1, %2;" : "=r"(r) : "f"(hi), "f"(lo));
    return r;
}
__device__ __forceinline__ void mwait(uint32_t mbar, uint32_t parity)
{
    asm volatile(
        "{\n\t.reg .pred P;\n\tWL_%=:\n\t"
        "mbarrier.try_wait.parity.shared.b64 P, [%0], %1;\n\t"
        "@!P bra WL_%=;\n\t}"
        :: "r"(mbar), "r"(parity) : "memory");
}
__device__ __forceinline__ void bulk_g2s(uint32_t dst, const void* src,
                                         uint32_t bytes, uint32_t mbar)
{
    asm volatile(
        "cp.async.bulk.shared::cta.global.mbarrier::complete_tx::bytes "
        "[%0], [%1], %2, [%3];"
        :: "r"(dst), "l"(src), "r"(bytes), "r"(mbar) : "memory");
}
__device__ __forceinline__ void ldsm4(uint32_t a, uint32_t* r)
{
    asm volatile("ldmatrix.sync.aligned.m8n8.x4.shared.b16 {%0,%1,%2,%3}, [%4];"
                 : "=r"(r[0]), "=r"(r[1]), "=r"(r[2]), "=r"(r[3]) : "r"(a));
}
#define MBAR_INIT(a, c) \
    asm volatile("mbarrier.init.shared.b64 [%0], %1;" :: "r"(a), "r"(c) : "memory")
#define MBAR_EXPECT(a, b) \
    asm volatile("mbarrier.arrive.expect_tx.shared.b64 _, [%0], %1;" \
                 :: "r"(a), "r"(b) : "memory")
#define MBAR_ARRIVE(a) \
    asm volatile("mbarrier.arrive.shared.b64 _, [%0];" :: "r"(a) : "memory")
#define STSV4(a, p) \
    asm volatile("st.shared.v4.b32 [%0], {%1,%2,%3,%4};" \
                 :: "r"(a), "r"((p)[0]), "r"((p)[1]), "r"((p)[2]), "r"((p)[3]) \
                 : "memory")
#define MMA(d, a, b) \
    asm volatile("mma.sync.aligned.m16n8k16.row.col.f32.bf16.bf16.f32 " \
                 "{%0,%1,%2,%3}, {%4,%5,%6,%7}, {%8,%9}, {%0,%1,%2,%3};" \
                 : "+f"((d)[0]), "+f"((d)[1]), "+f"((d)[2]), "+f"((d)[3]) \
                 : "r"((a)[0]), "r"((a)[1]), "r"((a)[2]), "r"((a)[3]), \
                   "r"((b)[0]), "r"((b)[1]))
#define BARC() asm volatile("bar.sync 1, 256;" ::: "memory")

// ---------------------------------------------------------------------------
// One layer: dst = relu( premix(A, src) @ W + b )
// 8 compute warps + 1 producer warp; 4-deep B-slab ring, no block syncs in
// the mainloop. A tile premixed+split into SMEM (hi/lo bf16, SW128).
// ---------------------------------------------------------------------------
template <int MT, int KK, int OO, int NCH, int WM, int WN, bool FINAL>
__global__ __launch_bounds__(288) void gemm_layer(
    const float* __restrict__ src, float* __restrict__ dst,
    const float* __restrict__ bias, const uint8_t* __restrict__ wsrc, int aidx)
{
    constexpr int ST = 4;                 // ring stages
    constexpr int NCK = KK / 32;
    constexpr int NNC = OO / NCH;
    constexpr int NSTEP = NNC * NCK;
    constexpr int WTN = NCH / WN;
    constexpr int MI = 2;
    constexpr int NJ = WTN / 8;
    constexpr int NJ4 = NJ / 2;
    constexpr int ASLAB = MT * 128;
    constexpr int BSLAB = NCH * 128;
    constexpr int ABYTES = NCK * ASLAB;
    constexpr int BPT = (MT == 128) ? 10 : 5;
    constexpr int VR = BPT * 12;

    extern __shared__ uint8_t smem[];
    __shared__ __align__(8) ull bars[2 * ST];   // full[0..3], empty[4..7]
    const uint32_t Ab = smem_u32(smem);
    const uint32_t Bb = Ab + ABYTES;
    const uint32_t fb = smem_u32(&bars[0]);
    const uint32_t eb = smem_u32(&bars[ST]);
    const int tid = threadIdx.x, l = tid & 31, w = tid >> 5;
    const int tile = blockIdx.x;

    if (tid == 0) {
#pragma unroll
        for (int s = 0; s < ST; s++) {
            MBAR_INIT(fb + 8 * s, 1);
            MBAR_INIT(eb + 8 * s, 8);
        }
    }
    __syncthreads();

    // ---------------- producer warp (warp 8) --------------------------------
    if (w == 8) {
        if (l == 0) {
            int eph = 1;
#pragma unroll 1
            for (int s = 0; s < NSTEP; s++) {
                const int st = s & (ST - 1);
                mwait(eb + 8 * st, eph);
                if (st == ST - 1) eph ^= 1;
                MBAR_EXPECT(fb + 8 * st, BSLAB);
                bulk_g2s(Bb + st * BSLAB, wsrc + (size_t)s * BSLAB, BSLAB,
                         fb + 8 * st);
            }
        }
        return;
    }

    // ---------------- premix A tile into SMEM (compute warps) ---------------
    {
        constexpr int TPR = 256 / MT;
        constexpr int PIECES = KK / (32 * TPR);
        const int r = tid / TPR, part = tid % TPR;
        const int nn = r % 12;
        const long batch = (long)tile * BPT + r / 12;
        const bool valid = (r < VR) && (batch < BTOT);
        const float* srow = src + (size_t)batch * 12 * KK;
        float am[12];
#pragma unroll
        for (int m = 0; m < 12; m++) am[m] = g_A[aidx + nn * 12 + m];
#pragma unroll 1
        for (int p = 0; p < PIECES; p++) {
            const int kc = part * PIECES + p;
            ull acc[16];
#pragma unroll
            for (int i = 0; i < 16; i++) acc[i] = 0ull;
            if (valid) {
#pragma unroll
                for (int m = 0; m < 12; m++) {
                    const float4* sp =
                        (const float4*)(srow + (size_t)m * KK + kc * 32);
                    ull amm = f2pack(am[m], am[m]);
#pragma unroll
                    for (int q = 0; q < 8; q++) {
                        float4 f = __ldg(sp + q);
                        f2fma(acc[2 * q], f2pack(f.x, f.y), amm);
                        f2fma(acc[2 * q + 1], f2pack(f.z, f.w), amm);
                    }
                }
            }
            uint32_t hw[16], lw[16];
#pragma unroll
            for (int i = 0; i < 16; i++) {
                float2 f = f2unp(acc[i]);
                uint32_t h = bf2pack(f.x, f.y);
                float v0 = __uint_as_float(h << 16);
                float v1 = __uint_as_float(h & 0xffff0000u);
                lw[i] = bf2pack(f.x - v0, f.y - v1);
                hw[i] = h;
            }
            const uint32_t base = Ab + kc * ASLAB;
#pragma unroll
            for (int q4 = 0; q4 < 4; q4++) {
                uint32_t off = (uint32_t)r * 64u + q4 * 16u;
                uint32_t sw = off ^ ((off >> 3) & 0x70u);
                STSV4(base + sw, hw + 4 * q4);
                STSV4(base + MT * 64 + sw, lw + 4 * q4);
            }
        }
    }
    BARC();   // compute warps only: A tile visible

    // ldmatrix per-lane byte offsets (within slab plane)
    const int wm = w / WN, wn = w % WN;
    uint32_t aoff[MI][2], boff[NJ4][2];
    {
        const int ar = wm * 32 + (l & 15);
        const int kh = l >> 4;
#pragma unroll
        for (int mi = 0; mi < MI; mi++)
#pragma unroll
            for (int k16 = 0; k16 < 2; k16++) {
                uint32_t off = (uint32_t)(ar + mi * 16) * 64u + k16 * 32u + kh * 16u;
                aoff[mi][k16] = off ^ ((off >> 3) & 0x70u);
            }
        const int br = wn * WTN + (l & 7) + 8 * (l >> 4);
        const int bk = (l >> 3) & 1;
#pragma unroll
        for (int j = 0; j < NJ4; j++)
#pragma unroll
            for (int k16 = 0; k16 < 2; k16++) {
                uint32_t off = (uint32_t)(br + j * 16) * 64u + k16 * 32u + bk * 16u;
                boff[j][k16] = off ^ ((off >> 3) & 0x70u);
            }
    }

    float acc[MI][NJ][4];
#pragma unroll
    for (int mi = 0; mi < MI; mi++)
#pragma unroll
        for (int nj = 0; nj < NJ; nj++)
#pragma unroll
            for (int q = 0; q < 4; q++) acc[mi][nj][q] = 0.f;

    long remv = ((long)BTOT - (long)tile * BPT) * 12;
    const int vrows = (remv > VR) ? VR : (int)remv;

    int fph = 0;
#pragma unroll 1
    for (int s = 0; s < NSTEP; s++) {
        const int st = s & (ST - 1);
        mwait(fb + 8 * st, fph);
        if (st == ST - 1) fph ^= 1;
        const uint32_t asl = Ab + (s % NCK) * ASLAB;
        const uint32_t bsl = Bb + st * BSLAB;
#pragma unroll
        for (int k16 = 0; k16 < 2; k16++) {
            uint32_t Ah[MI][4], Al[MI][4], Bh[NJ4][4], Bl[NJ4][4];
#pragma unroll
            for (int mi = 0; mi < MI; mi++) {
                ldsm4(asl + aoff[mi][k16], Ah[mi]);
                ldsm4(asl + MT * 64 + aoff[mi][k16], Al[mi]);
            }
#pragma unroll
            for (int j = 0; j < NJ4; j++) {
                ldsm4(bsl + boff[j][k16], Bh[j]);
                ldsm4(bsl + NCH * 64 + boff[j][k16], Bl[j]);
            }
            if (k16 == 1 && l == 0) MBAR_ARRIVE(eb + 8 * st);
#pragma unroll
            for (int mi = 0; mi < MI; mi++)
#pragma unroll
                for (int j = 0; j < NJ4; j++) {
                    MMA(acc[mi][2 * j], Ah[mi], &Bh[j][0]);
                    MMA(acc[mi][2 * j + 1], Ah[mi], &Bh[j][2]);
                    MMA(acc[mi][2 * j], Ah[mi], &Bl[j][0]);
                    MMA(acc[mi][2 * j + 1], Ah[mi], &Bl[j][2]);
                    MMA(acc[mi][2 * j], Al[mi], &Bh[j][0]);
                    MMA(acc[mi][2 * j + 1], Al[mi], &Bh[j][2]);
                }
        }
        if ((s % NCK) == NCK - 1) {
            const int nc = s / NCK;
            constexpr size_t OSTR = FINAL ? 40 : OO;
#pragma unroll
            for (int mi = 0; mi < MI; mi++)
#pragma unroll
                for (int nj = 0; nj < NJ; nj++) {
                    const int r0 = wm * 32 + mi * 16 + (l >> 2);
                    const int c0 = nc * NCH + wn * WTN + nj * 8 + 2 * (l & 3);
                    float2 bv = *(const float2*)(bias + c0);
                    float v0 = fmaxf(acc[mi][nj][0] + bv.x, 0.f);
                    float v1 = fmaxf(acc[mi][nj][1] + bv.y, 0.f);
                    float v2 = fmaxf(acc[mi][nj][2] + bv.x, 0.f);
                    float v3 = fmaxf(acc[mi][nj][3] + bv.y, 0.f);
                    const bool cok = (!FINAL) || (c0 < 40);
                    const size_t gr = (size_t)tile * VR + r0;
                    if (cok && r0 < vrows)
                        *(float2*)(dst + gr * OSTR + c0) = make_float2(v0, v1);
                    if (cok && r0 + 8 < vrows)
                        *(float2*)(dst + (gr + 8) * OSTR + c0) = make_float2(v2, v3);
#pragma unroll
                    for (int q = 0; q < 4; q++) acc[mi][nj][q] = 0.f;
                }
        }
    }
}

// ---------------------------------------------------------------------------
extern "C" void kernel_launch(void* const* d_in, const int* in_sizes, int n_in,
                              void* d_out, int out_size)
{
    const float* x    = (const float*)d_in[0];
    const float* adj  = (const float*)d_in[1];
    const float* nv1  = (const float*)d_in[2];
    const float* nv2  = (const float*)d_in[3];
    const float* W1   = (const float*)d_in[4];
    const float* att1 = (const float*)d_in[5];
    const float* b1   = (const float*)d_in[6];
    const float* W2   = (const float*)d_in[7];
    const float* att2 = (const float*)d_in[8];
    const float* b2   = (const float*)d_in[9];
    const float* W3   = (const float*)d_in[10];
    const float* att3 = (const float*)d_in[11];
    const float* b3   = (const float*)d_in[12];
    const float* W4   = (const float*)d_in[13];
    const float* att4 = (const float*)d_in[14];
    const float* b4   = (const float*)d_in[15];
    float* out = (float*)d_out;

    void *ph1, *ph2, *ph3, *pb4, *pw4, *pwp;
    cudaGetSymbolAddress(&ph1, g_h1);
    cudaGetSymbolAddress(&ph2, g_h2);
    cudaGetSymbolAddress(&ph3, g_h3);
    cudaGetSymbolAddress(&pb4, g_b4p);
    cudaGetSymbolAddress(&pw4, g_W4p);
    cudaGetSymbolAddress(&pwp, g_Wp);

    precompute_A<<<1, 64>>>(adj, nv1, nv2, att1, att2, att3, att4, b4);
    pad_W4<<<(128 * 64 + 255) / 256, 256>>>(W4, (float*)pw4);
    pack_Wsplit<<<(256 * 512 + 255) / 256, 256>>>(W1, 256, 512, 128, WP_L1);
    pack_Wsplit<<<(512 * 256 + 255) / 256, 256>>>(W2, 512, 256, 128, WP_L2);
    pack_Wsplit<<<(256 * 128 + 255) / 256, 256>>>(W3, 256, 128, 128, WP_L3);
    pack_Wsplit<<<(128 * 64 + 255) / 256, 256>>>((const float*)pw4, 128, 64, 64,
                                                 WP_L4);

    const uint8_t* wp = (const uint8_t*)pwp;
    const int SM1 = 8 * 128 * 128 + 4 * 128 * 128;   // 196608
    const int SM2 = 16 * 64 * 128 + 4 * 128 * 128;   // 196608
    const int SM3 = 8 * 128 * 128 + 4 * 128 * 128;   // 196608
    const int SM4 = 4 * 128 * 128 + 4 * 64 * 128;    // 98304
    cudaFuncSetAttribute((gemm_layer<128, 256, 512, 128, 4, 2, false>),
                         cudaFuncAttributeMaxDynamicSharedMemorySize, SM1);
    cudaFuncSetAttribute((gemm_layer<64, 512, 256, 128, 2, 4, false>),
                         cudaFuncAttributeMaxDynamicSharedMemorySize, SM2);
    cudaFuncSetAttribute((gemm_layer<128, 256, 128, 128, 4, 2, false>),
                         cudaFuncAttributeMaxDynamicSharedMemorySize, SM3);
    cudaFuncSetAttribute((gemm_layer<128, 128, 64, 64, 4, 2, true>),
                         cudaFuncAttributeMaxDynamicSharedMemorySize, SM4);

    const int T1 = 6554, T2 = 13108, T3 = 6554, T4 = 6554;
    gemm_layer<128, 256, 512, 128, 4, 2, false><<<T1, 288, SM1>>>(
        x, (float*)ph1, b1, wp + WP_L1, 0);
    gemm_layer<64, 512, 256, 128, 2, 4, false><<<T2, 288, SM2>>>(
        (const float*)ph1, (float*)ph2, b2, wp + WP_L2, 144);
    gemm_layer<128, 256, 128, 128, 4, 2, false><<<T3, 288, SM3>>>(
        (const float*)ph2, (float*)ph3, b3, wp + WP_L3, 288);
    gemm_layer<128, 128, 64, 64, 4, 2, true><<<T4, 288, SM4>>>(
        (const float*)ph3, out, (float*)pb4, wp + WP_L4, 432);
}

// round 14
// speedup vs baseline: 1.5327x; 1.0315x over previous
#include <cuda_runtime.h>
#include <cuda_bf16.h>
#include <cstdint>

typedef unsigned long long ull;

#define BTOT 65536

__device__ float g_A[576];          // 4 x 12x12 premix matrices
__device__ float g_b4p[64];         // padded layer-4 bias
__device__ float g_W4p[128 * 64];   // padded layer-4 W
// packed W slabs: per (n-chunk, k32): [hi NCH x 32 bf16 | lo ...], SW128
__device__ __align__(1024) uint8_t g_Wp[1245184];
#define WP_L1 0u
#define WP_L2 524288u
#define WP_L3 1048576u
#define WP_L4 1179648u

__device__ float g_h1[(size_t)BTOT * 12 * 512];
__device__ float g_h2[(size_t)BTOT * 12 * 256];
__device__ float g_h3[(size_t)BTOT * 12 * 128];

// ---------------------------------------------------------------------------
// single prep kernel: A premix matrices, padded b4, padded W4
// ---------------------------------------------------------------------------
__global__ void prep(const float* __restrict__ adj,
                     const float* __restrict__ nv1,
                     const float* __restrict__ nv2,
                     const float* __restrict__ a1,
                     const float* __restrict__ a2,
                     const float* __restrict__ a3,
                     const float* __restrict__ a4,
                     const float* __restrict__ b4,
                     const float* __restrict__ W4)
{
    int t = blockIdx.x * blockDim.x + threadIdx.x;
    if (t < 128 * 64) {
        int k = t / 64, o = t % 64;
        g_W4p[t] = (o < 40) ? W4[k * 40 + o] : 0.f;
    }
    if (blockIdx.x == 0) {
        int n = threadIdx.x;
        if (n < 64) g_b4p[n] = (n < 40) ? b4[n] : 0.f;
        if (n < 12) {
            float r[12];
            float mx = -1e30f;
            for (int m = 0; m < 12; m++) {
                float s = 0.f;
                for (int k = 0; k < 10; k++)
                    s += nv1[n * 10 + k] * nv2[k * 12 + m];
                s = fmaxf(s, 0.f);
                r[m] = s;
                mx = fmaxf(mx, s);
            }
            float den = 0.f;
            for (int m = 0; m < 12; m++) { r[m] = expf(r[m] - mx); den += r[m]; }
            float inv = 1.f / den;
            for (int m = 0; m < 12; m++) {
                float av = adj[n * 12 + m] + r[m] * inv;
                g_A[0 * 144 + n * 12 + m] = a1[n * 12 + m] * av;
                g_A[1 * 144 + n * 12 + m] = a2[n * 12 + m] * av;
                g_A[2 * 144 + n * 12 + m] = a3[n * 12 + m] * av;
                g_A[3 * 144 + n * 12 + m] = a4[n * 12 + m] * av;
            }
        }
    }
}

// W[K][O] row-major -> slabs [(nc,kc)]: hi plane [NCH][32k] + lo plane, SW128
__global__ void pack_Wsplit(const float* __restrict__ W, int K, int O, int NCH,
                            unsigned base)
{
    int idx = blockIdx.x * blockDim.x + threadIdx.x;
    if (idx >= K * O) return;
    int k = idx / O, o = idx % O;
    float w = W[idx];
    __nv_bfloat16 hi = __float2bfloat16(w);
    __nv_bfloat16 lo = __float2bfloat16(w - __bfloat162float(hi));
    int nc = o / NCH, ln = o % NCH, kc = k / 32, kk = k & 31;
    unsigned slab = base + (unsigned)(nc * (K / 32) + kc) * (unsigned)(NCH * 128);
    unsigned off = (unsigned)ln * 64u + (unsigned)kk * 2u;
    unsigned sw = off ^ ((off >> 3) & 0x70u);
    *(__nv_bfloat16*)(g_Wp + slab + sw) = hi;
    *(__nv_bfloat16*)(g_Wp + slab + (unsigned)(NCH * 64) + sw) = lo;
}

// ---------------------------------------------------------------------------
__device__ __forceinline__ uint32_t smem_u32(const void* p)
{
    uint32_t a;
    asm("{ .reg .u64 t; cvta.to.shared.u64 t, %1; cvt.u32.u64 %0, t; }"
        : "=r"(a) : "l"(p));
    return a;
}
__device__ __forceinline__ ull f2pack(float x, float y)
{
    ull r; asm("mov.b64 %0, {%1, %2};" : "=l"(r) : "f"(x), "f"(y)); return r;
}
__device__ __forceinline__ void f2fma(ull& d, ull a, ull b)
{
    asm("fma.rn.f32x2 %0, %1, %2, %0;" : "+l"(d) : "l"(a), "l"(b));
}
__device__ __forceinline__ float2 f2unp(ull v)
{
    float2 r; asm("mov.b64 {%0, %1}, %2;" : "=f"(r.x), "=f"(r.y) : "l"(v));
    return r;
}
__device__ __forceinline__ uint32_t bf2pack(float lo, float hi)
{
    uint32_t r;
    asm("cvt.rn.bf16x2.f32 %0, %1, %2;" : "=r"(r) : "f"(hi), "f"(lo));
    return r;
}
__device__ __forceinline__ void mwait(uint32_t mbar, uint32_t parity)
{
    asm volatile(
        "{\n\t.reg .pred P;\n\tWL_%=:\n\t"
        "mbarrier.try_wait.parity.shared.b64 P, [%0], %1;\n\t"
        "@!P bra WL_%=;\n\t}"
        :: "r"(mbar), "r"(parity) : "memory");
}
__device__ __forceinline__ void bulk_g2s(uint32_t dst, const void* src,
                                         uint32_t bytes, uint32_t mbar)
{
    asm volatile(
        "cp.async.bulk.shared::cta.global.mbarrier::complete_tx::bytes "
        "[%0], [%1], %2, [%3];"
        :: "r"(dst), "l"(src), "r"(bytes), "r"(mbar) : "memory");
}
__device__ __forceinline__ void ldsm4(uint32_t a, uint32_t* r)
{
    asm volatile("ldmatrix.sync.aligned.m8n8.x4.shared.b16 {%0,%1,%2,%3}, [%4];"
                 : "=r"(r[0]), "=r"(r[1]), "=r"(r[2]), "=r"(r[3]) : "r"(a));
}
#define MBAR_INIT(a, c) \
    asm volatile("mbarrier.init.shared.b64 [%0], %1;" :: "r"(a), "r"(c) : "memory")
#define MBAR_EXPECT(a, b) \
    asm volatile("mbarrier.arrive.expect_tx.shared.b64 _, [%0], %1;" \
                 :: "r"(a), "r"(b) : "memory")
#define MBAR_ARRIVE(a) \
    asm volatile("mbarrier.arrive.shared.b64 _, [%0];" :: "r"(a) : "memory")
#define STSV4(a, p) \
    asm volatile("st.shared.v4.b32 [%0], {%1,%2,%3,%4};" \
                 :: "r"(a), "r"((p)[0]), "r"((p)[1]), "r"((p)[2]), "r"((p)[3]) \
                 : "memory")
#define MMA(d, a, b) \
    asm volatile("mma.sync.aligned.m16n8k16.row.col.f32.bf16.bf16.f32 " \
                 "{%0,%1,%2,%3}, {%4,%5,%6,%7}, {%8,%9}, {%0,%1,%2,%3};" \
                 : "+f"((d)[0]), "+f"((d)[1]), "+f"((d)[2]), "+f"((d)[3]) \
                 : "r"((a)[0]), "r"((a)[1]), "r"((a)[2]), "r"((a)[3]), \
                   "r"((b)[0]), "r"((b)[1]))
#define BARC() asm volatile("bar.sync 1, 256;" ::: "memory")

// ---------------------------------------------------------------------------
// One layer: dst = relu( premix(A, src) @ W + b )
// 8 compute warps + 1 producer warp; ST-deep B-slab ring, no block syncs in
// the mainloop. A tile premixed+split into SMEM (hi/lo bf16, SW128).
// ---------------------------------------------------------------------------
template <int MT, int KK, int OO, int NCH, int WM, int WN, int ST, bool FINAL>
__global__ __launch_bounds__(288) void gemm_layer(
    const float* __restrict__ src, float* __restrict__ dst,
    const float* __restrict__ bias, const uint8_t* __restrict__ wsrc, int aidx)
{
    constexpr int NCK = KK / 32;
    constexpr int NNC = OO / NCH;
    constexpr int NSTEP = NNC * NCK;
    constexpr int WTN = NCH / WN;
    constexpr int MI = 2;
    constexpr int NJ = WTN / 8;
    constexpr int NJ4 = NJ / 2;
    constexpr int ASLAB = MT * 128;
    constexpr int BSLAB = NCH * 128;
    constexpr int ABYTES = NCK * ASLAB;
    constexpr int BPT = (MT == 128) ? 10 : 5;
    constexpr int VR = BPT * 12;

    extern __shared__ uint8_t smem[];
    __shared__ __align__(8) ull bars[2 * ST];   // full[0..ST-1], empty[ST..]
    const uint32_t Ab = smem_u32(smem);
    const uint32_t Bb = Ab + ABYTES;
    const uint32_t fb = smem_u32(&bars[0]);
    const uint32_t eb = smem_u32(&bars[ST]);
    const int tid = threadIdx.x, l = tid & 31, w = tid >> 5;
    const int tile = blockIdx.x;

    if (tid == 0) {
#pragma unroll
        for (int s = 0; s < ST; s++) {
            MBAR_INIT(fb + 8 * s, 1);
            MBAR_INIT(eb + 8 * s, 8);
        }
    }
    __syncthreads();

    // ---------------- producer warp (warp 8) --------------------------------
    if (w == 8) {
        if (l == 0) {
            int eph = 1;
#pragma unroll 1
            for (int s = 0; s < NSTEP; s++) {
                const int st = s % ST;
                mwait(eb + 8 * st, eph);
                if (st == ST - 1) eph ^= 1;
                MBAR_EXPECT(fb + 8 * st, BSLAB);
                bulk_g2s(Bb + st * BSLAB, wsrc + (size_t)s * BSLAB, BSLAB,
                         fb + 8 * st);
            }
        }
        return;
    }

    // ---------------- premix A tile into SMEM (compute warps) ---------------
    {
        constexpr int TPR = 256 / MT;
        constexpr int PIECES = KK / (32 * TPR);
        const int r = tid / TPR, part = tid % TPR;
        const int nn = r % 12;
        const long batch = (long)tile * BPT + r / 12;
        const bool valid = (r < VR) && (batch < BTOT);
        const float* srow = src + (size_t)batch * 12 * KK;
        float am[12];
#pragma unroll
        for (int m = 0; m < 12; m++) am[m] = g_A[aidx + nn * 12 + m];
#pragma unroll 1
        for (int p = 0; p < PIECES; p++) {
            const int kc = part * PIECES + p;
            ull acc[16];
#pragma unroll
            for (int i = 0; i < 16; i++) acc[i] = 0ull;
            if (valid) {
#pragma unroll
                for (int m = 0; m < 12; m++) {
                    const float4* sp =
                        (const float4*)(srow + (size_t)m * KK + kc * 32);
                    ull amm = f2pack(am[m], am[m]);
#pragma unroll
                    for (int q = 0; q < 8; q++) {
                        float4 f = __ldg(sp + q);
                        f2fma(acc[2 * q], f2pack(f.x, f.y), amm);
                        f2fma(acc[2 * q + 1], f2pack(f.z, f.w), amm);
                    }
                }
            }
            uint32_t hw[16], lw[16];
#pragma unroll
            for (int i = 0; i < 16; i++) {
                float2 f = f2unp(acc[i]);
                uint32_t h = bf2pack(f.x, f.y);
                float v0 = __uint_as_float(h << 16);
                float v1 = __uint_as_float(h & 0xffff0000u);
                lw[i] = bf2pack(f.x - v0, f.y - v1);
                hw[i] = h;
            }
            const uint32_t base = Ab + kc * ASLAB;
#pragma unroll
            for (int q4 = 0; q4 < 4; q4++) {
                uint32_t off = (uint32_t)r * 64u + q4 * 16u;
                uint32_t sw = off ^ ((off >> 3) & 0x70u);
                STSV4(base + sw, hw + 4 * q4);
                STSV4(base + MT * 64 + sw, lw + 4 * q4);
            }
        }
    }
    BARC();   // compute warps only: A tile visible

    // ldmatrix per-lane byte offsets (within slab plane)
    const int wm = w / WN, wn = w % WN;
    uint32_t aoff[MI][2], boff[NJ4][2];
    {
        const int ar = wm * 32 + (l & 15);
        const int kh = l >> 4;
#pragma unroll
        for (int mi = 0; mi < MI; mi++)
#pragma unroll
            for (int k16 = 0; k16 < 2; k16++) {
                uint32_t off = (uint32_t)(ar + mi * 16) * 64u + k16 * 32u + kh * 16u;
                aoff[mi][k16] = off ^ ((off >> 3) & 0x70u);
            }
        const int br = wn * WTN + (l & 7) + 8 * (l >> 4);
        const int bk = (l >> 3) & 1;
#pragma unroll
        for (int j = 0; j < NJ4; j++)
#pragma unroll
            for (int k16 = 0; k16 < 2; k16++) {
                uint32_t off = (uint32_t)(br + j * 16) * 64u + k16 * 32u + bk * 16u;
                boff[j][k16] = off ^ ((off >> 3) & 0x70u);
            }
    }

    float acc[MI][NJ][4];
#pragma unroll
    for (int mi = 0; mi < MI; mi++)
#pragma unroll
        for (int nj = 0; nj < NJ; nj++)
#pragma unroll
            for (int q = 0; q < 4; q++) acc[mi][nj][q] = 0.f;

    long remv = ((long)BTOT - (long)tile * BPT) * 12;
    const int vrows = (remv > VR) ? VR : (int)remv;

    int fph = 0;
#pragma unroll 1
    for (int s = 0; s < NSTEP; s++) {
        const int st = s % ST;
        mwait(fb + 8 * st, fph);
        if (st == ST - 1) fph ^= 1;
        const uint32_t asl = Ab + (s % NCK) * ASLAB;
        const uint32_t bsl = Bb + st * BSLAB;
#pragma unroll
        for (int k16 = 0; k16 < 2; k16++) {
            uint32_t Ah[MI][4], Al[MI][4], Bh[NJ4][4], Bl[NJ4][4];
#pragma unroll
            for (int mi = 0; mi < MI; mi++) {
                ldsm4(asl + aoff[mi][k16], Ah[mi]);
                ldsm4(asl + MT * 64 + aoff[mi][k16], Al[mi]);
            }
#pragma unroll
            for (int j = 0; j < NJ4; j++) {
                ldsm4(bsl + boff[j][k16], Bh[j]);
                ldsm4(bsl + NCH * 64 + boff[j][k16], Bl[j]);
            }
            if (k16 == 1 && l == 0) MBAR_ARRIVE(eb + 8 * st);
#pragma unroll
            for (int mi = 0; mi < MI; mi++)
#pragma unroll
                for (int j = 0; j < NJ4; j++) {
                    MMA(acc[mi][2 * j], Ah[mi], &Bh[j][0]);
                    MMA(acc[mi][2 * j + 1], Ah[mi], &Bh[j][2]);
                    MMA(acc[mi][2 * j], Ah[mi], &Bl[j][0]);
                    MMA(acc[mi][2 * j + 1], Ah[mi], &Bl[j][2]);
                    MMA(acc[mi][2 * j], Al[mi], &Bh[j][0]);
                    MMA(acc[mi][2 * j + 1], Al[mi], &Bh[j][2]);
                }
        }
        if ((s % NCK) == NCK - 1) {
            const int nc = s / NCK;
            constexpr size_t OSTR = FINAL ? 40 : OO;
#pragma unroll
            for (int mi = 0; mi < MI; mi++)
#pragma unroll
                for (int nj = 0; nj < NJ; nj++) {
                    const int r0 = wm * 32 + mi * 16 + (l >> 2);
                    const int c0 = nc * NCH + wn * WTN + nj * 8 + 2 * (l & 3);
                    float2 bv = *(const float2*)(bias + c0);
                    float v0 = fmaxf(acc[mi][nj][0] + bv.x, 0.f);
                    float v1 = fmaxf(acc[mi][nj][1] + bv.y, 0.f);
                    float v2 = fmaxf(acc[mi][nj][2] + bv.x, 0.f);
                    float v3 = fmaxf(acc[mi][nj][3] + bv.y, 0.f);
                    const bool cok = (!FINAL) || (c0 < 40);
                    const size_t gr = (size_t)tile * VR + r0;
                    if (cok && r0 < vrows)
                        *(float2*)(dst + gr * OSTR + c0) = make_float2(v0, v1);
                    if (cok && r0 + 8 < vrows)
                        *(float2*)(dst + (gr + 8) * OSTR + c0) = make_float2(v2, v3);
#pragma unroll
                    for (int q = 0; q < 4; q++) acc[mi][nj][q] = 0.f;
                }
        }
    }
}

// ---------------------------------------------------------------------------
extern "C" void kernel_launch(void* const* d_in, const int* in_sizes, int n_in,
                              void* d_out, int out_size)
{
    const float* x    = (const float*)d_in[0];
    const float* adj  = (const float*)d_in[1];
    const float* nv1  = (const float*)d_in[2];
    const float* nv2  = (const float*)d_in[3];
    const float* W1   = (const float*)d_in[4];
    const float* att1 = (const float*)d_in[5];
    const float* b1   = (const float*)d_in[6];
    const float* W2   = (const float*)d_in[7];
    const float* att2 = (const float*)d_in[8];
    const float* b2   = (const float*)d_in[9];
    const float* W3   = (const float*)d_in[10];
    const float* att3 = (const float*)d_in[11];
    const float* b3   = (const float*)d_in[12];
    const float* W4   = (const float*)d_in[13];
    const float* att4 = (const float*)d_in[14];
    const float* b4   = (const float*)d_in[15];
    float* out = (float*)d_out;

    void *ph1, *ph2, *ph3, *pb4, *pw4, *pwp;
    cudaGetSymbolAddress(&ph1, g_h1);
    cudaGetSymbolAddress(&ph2, g_h2);
    cudaGetSymbolAddress(&ph3, g_h3);
    cudaGetSymbolAddress(&pb4, g_b4p);
    cudaGetSymbolAddress(&pw4, g_W4p);
    cudaGetSymbolAddress(&pwp, g_Wp);

    // 5 prep launches total -> 6th launch (profiled by ncu -s 5 -c 1) = gemm L1
    prep<<<32, 256>>>(adj, nv1, nv2, att1, att2, att3, att4, b4, W4);
    pack_Wsplit<<<(256 * 512 + 255) / 256, 256>>>(W1, 256, 512, 128, WP_L1);
    pack_Wsplit<<<(512 * 256 + 255) / 256, 256>>>(W2, 512, 256, 256, WP_L2);
    pack_Wsplit<<<(256 * 128 + 255) / 256, 256>>>(W3, 256, 128, 128, WP_L3);
    pack_Wsplit<<<(128 * 64 + 255) / 256, 256>>>((const float*)pw4, 128, 64, 64,
                                                 WP_L4);

    const uint8_t* wp = (const uint8_t*)pwp;
    const int SM1 = 8 * 16384 + 4 * 16384;    // 196608
    const int SM2 = 16 * 8192 + 3 * 32768;    // 229376
    const int SM3 = 8 * 16384 + 4 * 16384;    // 196608
    const int SM4 = 4 * 16384 + 4 * 8192;     // 98304
    cudaFuncSetAttribute((gemm_layer<128, 256, 512, 128, 4, 2, 4, false>),
                         cudaFuncAttributeMaxDynamicSharedMemorySize, SM1);
    cudaFuncSetAttribute((gemm_layer<64, 512, 256, 256, 2, 4, 3, false>),
                         cudaFuncAttributeMaxDynamicSharedMemorySize, SM2);
    cudaFuncSetAttribute((gemm_layer<128, 256, 128, 128, 4, 2, 4, false>),
                         cudaFuncAttributeMaxDynamicSharedMemorySize, SM3);
    cudaFuncSetAttribute((gemm_layer<128, 128, 64, 64, 4, 2, 4, true>),
                         cudaFuncAttributeMaxDynamicSharedMemorySize, SM4);

    const int T1 = 6554, T2 = 13108, T3 = 6554, T4 = 6554;
    gemm_layer<128, 256, 512, 128, 4, 2, 4, false><<<T1, 288, SM1>>>(
        x, (float*)ph1, b1, wp + WP_L1, 0);
    gemm_layer<64, 512, 256, 256, 2, 4, 3, false><<<T2, 288, SM2>>>(
        (const float*)ph1, (float*)ph2, b2, wp + WP_L2, 144);
    gemm_layer<128, 256, 128, 128, 4, 2, 4, false><<<T3, 288, SM3>>>(
        (const float*)ph2, (float*)ph3, b3, wp + WP_L3, 288);
    gemm_layer<128, 128, 64, 64, 4, 2, 4, true><<<T4, 288, SM4>>>(
        (const float*)ph3, out, (float*)pb4, wp + WP_L4, 432);
}

// round 16
// speedup vs baseline: 2.0236x; 1.3203x over previous
#include <cuda_runtime.h>
#include <cuda_bf16.h>
#include <cstdint>

typedef unsigned long long ull;

#define BTOT 65536

__device__ float g_A[576];          // 4 x 12x12 premix matrices
__device__ float g_b4p[64];         // padded layer-4 bias
__device__ float g_W4p[128 * 64];   // padded layer-4 W
// packed W slabs: per (n-chunk, k32): [hi NCH x 32 bf16 | lo ...], SW128
__device__ __align__(1024) uint8_t g_Wp[1245184];
#define WP_L1 0u
#define WP_L2 524288u
#define WP_L3 1048576u
#define WP_L4 1179648u

__device__ float g_h1[(size_t)BTOT * 12 * 512];
__device__ float g_h2[(size_t)BTOT * 12 * 256];
__device__ float g_h3[(size_t)BTOT * 12 * 128];

// ---------------------------------------------------------------------------
// prep: A premix matrices, padded b4, padded W4
// ---------------------------------------------------------------------------
__global__ void prep(const float* __restrict__ adj,
                     const float* __restrict__ nv1,
                     const float* __restrict__ nv2,
                     const float* __restrict__ a1,
                     const float* __restrict__ a2,
                     const float* __restrict__ a3,
                     const float* __restrict__ a4,
                     const float* __restrict__ b4,
                     const float* __restrict__ W4)
{
    int t = blockIdx.x * blockDim.x + threadIdx.x;
    if (t < 128 * 64) {
        int k = t / 64, o = t % 64;
        g_W4p[t] = (o < 40) ? W4[k * 40 + o] : 0.f;
    }
    if (blockIdx.x == 0) {
        int n = threadIdx.x;
        if (n < 64) g_b4p[n] = (n < 40) ? b4[n] : 0.f;
        if (n < 12) {
            float r[12];
            float mx = -1e30f;
            for (int m = 0; m < 12; m++) {
                float s = 0.f;
                for (int k = 0; k < 10; k++)
                    s += nv1[n * 10 + k] * nv2[k * 12 + m];
                s = fmaxf(s, 0.f);
                r[m] = s;
                mx = fmaxf(mx, s);
            }
            float den = 0.f;
            for (int m = 0; m < 12; m++) { r[m] = expf(r[m] - mx); den += r[m]; }
            float inv = 1.f / den;
            for (int m = 0; m < 12; m++) {
                float av = adj[n * 12 + m] + r[m] * inv;
                g_A[0 * 144 + n * 12 + m] = a1[n * 12 + m] * av;
                g_A[1 * 144 + n * 12 + m] = a2[n * 12 + m] * av;
                g_A[2 * 144 + n * 12 + m] = a3[n * 12 + m] * av;
                g_A[3 * 144 + n * 12 + m] = a4[n * 12 + m] * av;
            }
        }
    }
}

// all four W packs in one kernel (W4 reads g_W4p written by prep)
__global__ void pack_all(const float* __restrict__ W1,
                         const float* __restrict__ W2,
                         const float* __restrict__ W3)
{
    int idx = blockIdx.x * blockDim.x + threadIdx.x;
    const float* W;
    int K, O, NCH, rel;
    unsigned base;
    if (idx < 131072)      { W = W1;     K = 256; O = 512; NCH = 128; base = WP_L1; rel = idx; }
    else if (idx < 262144) { W = W2;     K = 512; O = 256; NCH = 256; base = WP_L2; rel = idx - 131072; }
    else if (idx < 294912) { W = W3;     K = 256; O = 128; NCH = 128; base = WP_L3; rel = idx - 262144; }
    else if (idx < 303104) { W = g_W4p;  K = 128; O = 64;  NCH = 64;  base = WP_L4; rel = idx - 294912; }
    else return;
    int k = rel / O, o = rel % O;
    float w = W[rel];
    __nv_bfloat16 hi = __float2bfloat16(w);
    __nv_bfloat16 lo = __float2bfloat16(w - __bfloat162float(hi));
    int nc = o / NCH, ln = o % NCH, kc = k / 32, kk = k & 31;
    unsigned slab = base + (unsigned)(nc * (K / 32) + kc) * (unsigned)(NCH * 128);
    unsigned off = (unsigned)ln * 64u + (unsigned)kk * 2u;
    unsigned sw = off ^ ((off >> 3) & 0x70u);
    *(__nv_bfloat16*)(g_Wp + slab + sw) = hi;
    *(__nv_bfloat16*)(g_Wp + slab + (unsigned)(NCH * 64) + sw) = lo;
}

// ---------------------------------------------------------------------------
__device__ __forceinline__ uint32_t smem_u32(const void* p)
{
    uint32_t a;
    asm("{ .reg .u64 t; cvta.to.shared.u64 t, %1; cvt.u32.u64 %0, t; }"
        : "=r"(a) : "l"(p));
    return a;
}
__device__ __forceinline__ void f2fma(ull& d, ull a, ull b)
{
    asm("fma.rn.f32x2 %0, %1, %2, %0;" : "+l"(d) : "l"(a), "l"(b));
}
__device__ __forceinline__ float2 f2unp(ull v)
{
    float2 r; asm("mov.b64 {%0, %1}, %2;" : "=f"(r.x), "=f"(r.y) : "l"(v));
    return r;
}
__device__ __forceinline__ uint32_t bf2pack(float lo, float hi)
{
    uint32_t r;
    asm("cvt.rn.bf16x2.f32 %0, %1, %2;" : "=r"(r) : "f"(hi), "f"(lo));
    return r;
}
__device__ __forceinline__ void mwait(uint32_t mbar, uint32_t parity)
{
    asm volatile(
        "{\n\t.reg .pred P;\n\tWL_%=:\n\t"
        "mbarrier.try_wait.parity.shared.b64 P, [%0], %1;\n\t"
        "@!P bra WL_%=;\n\t}"
        :: "r"(mbar), "r"(parity) : "memory");
}
__device__ __forceinline__ void bulk_g2s(uint32_t dst, const void* src,
                                         uint32_t bytes, uint32_t mbar)
{
    asm volatile(
        "cp.async.bulk.shared::cta.global.mbarrier::complete_tx::bytes "
        "[%0], [%1], %2, [%3];"
        :: "r"(dst), "l"(src), "r"(bytes), "r"(mbar) : "memory");
}
__device__ __forceinline__ void ldsm4(uint32_t a, uint32_t* r)
{
    asm volatile("ldmatrix.sync.aligned.m8n8.x4.shared.b16 {%0,%1,%2,%3}, [%4];"
                 : "=r"(r[0]), "=r"(r[1]), "=r"(r[2]), "=r"(r[3]) : "r"(a));
}
#define MBAR_INIT(a, c) \
    asm volatile("mbarrier.init.shared.b64 [%0], %1;" :: "r"(a), "r"(c) : "memory")
#define MBAR_EXPECT(a, b) \
    asm volatile("mbarrier.arrive.expect_tx.shared.b64 _, [%0], %1;" \
                 :: "r"(a), "r"(b) : "memory")
#define MBAR_ARRIVE(a) \
    asm volatile("mbarrier.arrive.shared.b64 _, [%0];" :: "r"(a) : "memory")
#define STS32(a, v) \
    asm volatile("st.shared.b32 [%0], %1;" :: "r"(a), "r"(v) : "memory")
#define MMA(d, a, b) \
    asm volatile("mma.sync.aligned.m16n8k16.row.col.f32.bf16.bf16.f32 " \
                 "{%0,%1,%2,%3}, {%4,%5,%6,%7}, {%8,%9}, {%0,%1,%2,%3};" \
                 : "+f"((d)[0]), "+f"((d)[1]), "+f"((d)[2]), "+f"((d)[3]) \
                 : "r"((a)[0]), "r"((a)[1]), "r"((a)[2]), "r"((a)[3]), \
                   "r"((b)[0]), "r"((b)[1]))
#define BARC() asm volatile("bar.sync 1, 256;" ::: "memory")

// ---------------------------------------------------------------------------
// One layer: dst = relu( premix(A, src) @ W + b )
// 8 compute warps + 1 producer warp; ST-deep B-slab ring.
// Premix v2: per k-chunk, source staged ONCE through SMEM (coalesced LDG,
// register-pipelined), then mixed from SMEM -> 1x global read (was 12x).
// ---------------------------------------------------------------------------
template <int MT, int KK, int OO, int NCH, int WM, int WN, int ST, bool FINAL>
__global__ __launch_bounds__(288) void gemm_layer(
    const float* __restrict__ src, float* __restrict__ dst,
    const float* __restrict__ bias, const uint8_t* __restrict__ wsrc, int aidx)
{
    constexpr int NCK = KK / 32;
    constexpr int NNC = OO / NCH;
    constexpr int NSTEP = NNC * NCK;
    constexpr int WTN = NCH / WN;
    constexpr int MI = 2;
    constexpr int NJ = WTN / 8;
    constexpr int NJ4 = NJ / 2;
    constexpr int ASLAB = MT * 128;
    constexpr int BSLAB = NCH * 128;
    constexpr int ABYTES = NCK * ASLAB;
    constexpr int BPT = (MT == 128) ? 10 : 5;
    constexpr int VR = BPT * 12;
    constexpr int NP = (VR * 8 + 255) / 256;   // float4 stage loads per thread

    extern __shared__ uint8_t smem[];
    __shared__ __align__(8) ull bars[2 * ST];
    __shared__ __align__(8) float2 Ash2[144];
    const uint32_t Ab = smem_u32(smem);
    const uint32_t Bb = Ab + ABYTES;
    float* stage = (float*)(smem + ABYTES + ST * BSLAB);
    const uint32_t fb = smem_u32(&bars[0]);
    const uint32_t eb = smem_u32(&bars[ST]);
    const int tid = threadIdx.x, l = tid & 31, w = tid >> 5;
    const int tile = blockIdx.x;

    if (tid == 0) {
#pragma unroll
        for (int s = 0; s < ST; s++) {
            MBAR_INIT(fb + 8 * s, 1);
            MBAR_INIT(eb + 8 * s, 8);
        }
    }
    if (tid < 144) {
        float a = g_A[aidx + tid];
        Ash2[tid] = make_float2(a, a);
    }
    __syncthreads();

    // ---------------- producer warp (warp 8) --------------------------------
    if (w == 8) {
        if (l == 0) {
            int eph = 1;
#pragma unroll 1
            for (int s = 0; s < NSTEP; s++) {
                const int st = s % ST;
                mwait(eb + 8 * st, eph);
                if (st == ST - 1) eph ^= 1;
                MBAR_EXPECT(fb + 8 * st, BSLAB);
                bulk_g2s(Bb + st * BSLAB, wsrc + (size_t)s * BSLAB, BSLAB,
                         fb + 8 * st);
            }
        }
        return;
    }

    long remv = ((long)BTOT - (long)tile * BPT) * 12;
    const int vrows = (remv > VR) ? VR : (int)remv;
    const size_t rowbase = (size_t)tile * VR;

    // ---------------- premix A tile via SMEM staging ------------------------
    {
        const int pb = tid >> 4, pcg = tid & 15;
        const bool pok = tid < BPT * 16;
        float4 pf[NP];
        // preload chunk 0
#pragma unroll
        for (int j = 0; j < NP; j++) {
            int i = tid + j * 256;
            float4 v = make_float4(0.f, 0.f, 0.f, 0.f);
            if (i < VR * 8) {
                int row = i >> 3, q = i & 7;
                if (row < vrows)
                    v = __ldg((const float4*)(src + (rowbase + row) * KK + q * 4));
            }
            pf[j] = v;
        }
#pragma unroll 1
        for (int c = 0; c < NCK; c++) {
            // store staged chunk
#pragma unroll
            for (int j = 0; j < NP; j++) {
                int i = tid + j * 256;
                if (i < VR * 8) {
                    int row = i >> 3, q = i & 7;
                    *(float4*)(stage + row * 32 + q * 4) = pf[j];
                }
            }
            BARC();
            // prefetch next chunk (LDG latency hidden under mixing)
            if (c + 1 < NCK) {
#pragma unroll
                for (int j = 0; j < NP; j++) {
                    int i = tid + j * 256;
                    float4 v = make_float4(0.f, 0.f, 0.f, 0.f);
                    if (i < VR * 8) {
                        int row = i >> 3, q = i & 7;
                        if (row < vrows)
                            v = __ldg((const float4*)(src + (rowbase + row) * KK
                                                      + (c + 1) * 32 + q * 4));
                    }
                    pf[j] = v;
                }
            }
            if (pok) {
                ull vm[12];
#pragma unroll
                for (int m = 0; m < 12; m++)
                    vm[m] = *(const ull*)(stage + (pb * 12 + m) * 32 + pcg * 2);
                const uint32_t abase = Ab + c * ASLAB;
#pragma unroll
                for (int n = 0; n < 12; n++) {
                    ull acc = 0ull;
#pragma unroll
                    for (int m = 0; m < 12; m++)
                        f2fma(acc, vm[m], *(const ull*)&Ash2[n * 12 + m]);
                    float2 f = f2unp(acc);
                    uint32_t h = bf2pack(f.x, f.y);
                    float v0 = __uint_as_float(h << 16);
                    float v1 = __uint_as_float(h & 0xffff0000u);
                    uint32_t lo = bf2pack(f.x - v0, f.y - v1);
                    uint32_t off = (uint32_t)(pb * 12 + n) * 64u + pcg * 4u;
                    uint32_t sw = off ^ ((off >> 3) & 0x70u);
                    STS32(abase + sw, h);
                    STS32(abase + MT * 64 + sw, lo);
                }
            }
            BARC();
        }
    }

    // ldmatrix per-lane byte offsets (within slab plane)
    const int wm = w / WN, wn = w % WN;
    uint32_t aoff[MI][2], boff[NJ4][2];
    {
        const int ar = wm * 32 + (l & 15);
        const int kh = l >> 4;
#pragma unroll
        for (int mi = 0; mi < MI; mi++)
#pragma unroll
            for (int k16 = 0; k16 < 2; k16++) {
                uint32_t off = (uint32_t)(ar + mi * 16) * 64u + k16 * 32u + kh * 16u;
                aoff[mi][k16] = off ^ ((off >> 3) & 0x70u);
            }
        const int br = wn * WTN + (l & 7) + 8 * (l >> 4);
        const int bk = (l >> 3) & 1;
#pragma unroll
        for (int j = 0; j < NJ4; j++)
#pragma unroll
            for (int k16 = 0; k16 < 2; k16++) {
                uint32_t off = (uint32_t)(br + j * 16) * 64u + k16 * 32u + bk * 16u;
                boff[j][k16] = off ^ ((off >> 3) & 0x70u);
            }
    }

    float acc[MI][NJ][4];
#pragma unroll
    for (int mi = 0; mi < MI; mi++)
#pragma unroll
        for (int nj = 0; nj < NJ; nj++)
#pragma unroll
            for (int q = 0; q < 4; q++) acc[mi][nj][q] = 0.f;

    int fph = 0;
#pragma unroll 1
    for (int s = 0; s < NSTEP; s++) {
        const int st = s % ST;
        mwait(fb + 8 * st, fph);
        if (st == ST - 1) fph ^= 1;
        const uint32_t asl = Ab + (s % NCK) * ASLAB;
        const uint32_t bsl = Bb + st * BSLAB;
#pragma unroll
        for (int k16 = 0; k16 < 2; k16++) {
            uint32_t Ah[MI][4], Al[MI][4], Bh[NJ4][4], Bl[NJ4][4];
#pragma unroll
            for (int mi = 0; mi < MI; mi++) {
                ldsm4(asl + aoff[mi][k16], Ah[mi]);
                ldsm4(asl + MT * 64 + aoff[mi][k16], Al[mi]);
            }
#pragma unroll
            for (int j = 0; j < NJ4; j++) {
                ldsm4(bsl + boff[j][k16], Bh[j]);
                ldsm4(bsl + NCH * 64 + boff[j][k16], Bl[j]);
            }
            if (k16 == 1 && l == 0) MBAR_ARRIVE(eb + 8 * st);
#pragma unroll
            for (int mi = 0; mi < MI; mi++)
#pragma unroll
                for (int j = 0; j < NJ4; j++) {
                    MMA(acc[mi][2 * j], Ah[mi], &Bh[j][0]);
                    MMA(acc[mi][2 * j + 1], Ah[mi], &Bh[j][2]);
                    MMA(acc[mi][2 * j], Ah[mi], &Bl[j][0]);
                    MMA(acc[mi][2 * j + 1], Ah[mi], &Bl[j][2]);
                    MMA(acc[mi][2 * j], Al[mi], &Bh[j][0]);
                    MMA(acc[mi][2 * j + 1], Al[mi], &Bh[j][2]);
                }
        }
        if ((s % NCK) == NCK - 1) {
            const int nc = s / NCK;
            constexpr size_t OSTR = FINAL ? 40 : OO;
#pragma unroll
            for (int mi = 0; mi < MI; mi++)
#pragma unroll
                for (int nj = 0; nj < NJ; nj++) {
                    const int r0 = wm * 32 + mi * 16 + (l >> 2);
                    const int c0 = nc * NCH + wn * WTN + nj * 8 + 2 * (l & 3);
                    float2 bv = *(const float2*)(bias + c0);
                    float v0 = fmaxf(acc[mi][nj][0] + bv.x, 0.f);
                    float v1 = fmaxf(acc[mi][nj][1] + bv.y, 0.f);
                    float v2 = fmaxf(acc[mi][nj][2] + bv.x, 0.f);
                    float v3 = fmaxf(acc[mi][nj][3] + bv.y, 0.f);
                    const bool cok = (!FINAL) || (c0 < 40);
                    const size_t gr = rowbase + r0;
                    if (cok && r0 < vrows)
                        *(float2*)(dst + gr * OSTR + c0) = make_float2(v0, v1);
                    if (cok && r0 + 8 < vrows)
                        *(float2*)(dst + (gr + 8) * OSTR + c0) = make_float2(v2, v3);
#pragma unroll
                    for (int q = 0; q < 4; q++) acc[mi][nj][q] = 0.f;
                }
        }
    }
}

// ---------------------------------------------------------------------------
extern "C" void kernel_launch(void* const* d_in, const int* in_sizes, int n_in,
                              void* d_out, int out_size)
{
    const float* x    = (const float*)d_in[0];
    const float* adj  = (const float*)d_in[1];
    const float* nv1  = (const float*)d_in[2];
    const float* nv2  = (const float*)d_in[3];
    const float* W1   = (const float*)d_in[4];
    const float* att1 = (const float*)d_in[5];
    const float* b1   = (const float*)d_in[6];
    const float* W2   = (const float*)d_in[7];
    const float* att2 = (const float*)d_in[8];
    const float* b2   = (const float*)d_in[9];
    const float* W3   = (const float*)d_in[10];
    const float* att3 = (const float*)d_in[11];
    const float* b3   = (const float*)d_in[12];
    const float* W4   = (const float*)d_in[13];
    const float* att4 = (const float*)d_in[14];
    const float* b4   = (const float*)d_in[15];
    float* out = (float*)d_out;

    void *ph1, *ph2, *ph3, *pb4, *pwp;
    cudaGetSymbolAddress(&ph1, g_h1);
    cudaGetSymbolAddress(&ph2, g_h2);
    cudaGetSymbolAddress(&ph3, g_h3);
    cudaGetSymbolAddress(&pb4, g_b4p);
    cudaGetSymbolAddress(&pwp, g_Wp);

    prep<<<32, 256>>>(adj, nv1, nv2, att1, att2, att3, att4, b4, W4);
    pack_all<<<1184, 256>>>(W1, W2, W3);

    const uint8_t* wp = (const uint8_t*)pwp;
    const int SM1 = 8 * 16384 + 4 * 16384 + 15360;   // 211968
    const int SM2 = 16 * 8192 + 2 * 32768 + 7680;    // 204288
    const int SM3 = 8 * 16384 + 4 * 16384 + 15360;   // 211968
    const int SM4 = 4 * 16384 + 4 * 8192 + 15360;    // 113664
    cudaFuncSetAttribute((gemm_layer<128, 256, 512, 128, 4, 2, 4, false>),
                         cudaFuncAttributeMaxDynamicSharedMemorySize, SM1);
    cudaFuncSetAttribute((gemm_layer<64, 512, 256, 256, 2, 4, 2, false>),
                         cudaFuncAttributeMaxDynamicSharedMemorySize, SM2);
    cudaFuncSetAttribute((gemm_layer<128, 256, 128, 128, 4, 2, 4, false>),
                         cudaFuncAttributeMaxDynamicSharedMemorySize, SM3);
    cudaFuncSetAttribute((gemm_layer<128, 128, 64, 64, 4, 2, 4, true>),
                         cudaFuncAttributeMaxDynamicSharedMemorySize, SM4);

    const int T1 = 6554, T2 = 13108, T3 = 6554, T4 = 6554;
    gemm_layer<128, 256, 512, 128, 4, 2, 4, false><<<T1, 288, SM1>>>(
        x, (float*)ph1, b1, wp + WP_L1, 0);
    gemm_layer<64, 512, 256, 256, 2, 4, 2, false><<<T2, 288, SM2>>>(
        (const float*)ph1, (float*)ph2, b2, wp + WP_L2, 144);
    gemm_layer<128, 256, 128, 128, 4, 2, 4, false><<<T3, 288, SM3>>>(
        (const float*)ph2, (float*)ph3, b3, wp + WP_L3, 288);
    gemm_layer<128, 128, 64, 64, 4, 2, 4, true><<<T4, 288, SM4>>>(
        (const float*)ph3, out, (float*)pb4, wp + WP_L4, 432);
}